// round 10
// baseline (speedup 1.0000x reference)
#include <cuda_runtime.h>
#include <cuda_fp16.h>
#include <cstdint>

#define N_NODES 100000
#define E_EDGES 1600000
#define E2 (E_EDGES + N_NODES)   // 1,700,000 with self loops
#define HID 64
#define IN_DIM 128
#define NEG_SLOPE 0.2f
#define SCAN_CHUNK 1024
#define NCHUNKS ((N_NODES + SCAN_CHUNK - 1) / SCAN_CHUNK)   // 98

// ---------------- scratch (device globals) ------------------------------------
__device__ __align__(16) __half g_h16[(size_t)N_NODES * HID]; // fp16 features (gathered)
__device__ float g_agg[(size_t)N_NODES * HID];    // layer1 output: elu(agg+b1)
__device__ float g_as[N_NODES], g_ad[N_NODES];    // per-node alpha_src / alpha_dst
__device__ int   g_csr_src[E2];                   // dst-sorted src indices
__device__ int   g_cnt[N_NODES];                  // per-dst degree histogram
__device__ int   g_cur[N_NODES];                  // scatter cursors
__device__ int   g_base[N_NODES];                 // per-chunk exclusive scan
__device__ int   g_part[128], g_partsc[128];      // chunk partials / scanned
__device__ int   g_rowptr[N_NODES + 1];           // CSR row pointers
__device__ int   g_is64;                          // edge_index dtype flag

// ---------------- helpers -----------------------------------------------------
__device__ __forceinline__ float elu_f(float v) { return v > 0.f ? v : expm1f(v); }

__device__ __forceinline__ int warp_incl_scan(int v) {
    int lane = threadIdx.x & 31;
#pragma unroll
    for (int o = 1; o < 32; o <<= 1) {
        int t = __shfl_up_sync(0xffffffffu, v, o);
        if (lane >= o) v += t;
    }
    return v;
}

// ---------------- dtype probe + zero counters ---------------------------------
__global__ void k_probe(const int* ei32) {
    __shared__ int nz;
    if (threadIdx.x == 0) nz = 0;
    __syncthreads();
    int any = 0;
    for (int i = threadIdx.x; i < 2048; i += 256)
        any |= (ei32[2 * i + 1] != 0);
    if (any) atomicOr(&nz, 1);
    __syncthreads();
    if (threadIdx.x == 0) g_is64 = (nz == 0) ? 1 : 0;
}

__global__ void k_zero() {
    int i = blockIdx.x * blockDim.x + threadIdx.x;
    if (i < N_NODES) { g_cnt[i] = 0; g_cur[i] = 0; }
}

// ---------------- histogram by dst (reads edge_index directly) ----------------
__global__ void k_hist(const void* ei) {
    int i = blockIdx.x * blockDim.x + threadIdx.x;
    if (i >= E2) return;
    int d;
    if (i < E_EDGES) {
        d = g_is64 ? (int)((const long long*)ei)[E_EDGES + i]
                   : ((const int*)ei)[E_EDGES + i];
    } else {
        d = i - E_EDGES;
    }
    atomicAdd(&g_cnt[d], 1);
}

// ---------------- two-level scan of histogram ---------------------------------
__global__ __launch_bounds__(SCAN_CHUNK) void k_scan1() {
    __shared__ int wsum[32];
    int b = blockIdx.x;
    int i = b * SCAN_CHUNK + threadIdx.x;
    int lane = threadIdx.x & 31, wid = threadIdx.x >> 5;
    int v = (i < N_NODES) ? g_cnt[i] : 0;
    int inc = warp_incl_scan(v);
    if (lane == 31) wsum[wid] = inc;
    __syncthreads();
    if (wid == 0) wsum[lane] = warp_incl_scan(wsum[lane]);
    __syncthreads();
    int off = wid ? wsum[wid - 1] : 0;
    if (i < N_NODES) g_base[i] = off + inc - v;
    if (threadIdx.x == SCAN_CHUNK - 1) g_part[b] = wsum[31];
}

__global__ __launch_bounds__(32) void k_scan2() {
    int lane = threadIdx.x;
    int v0 = g_part[lane * 4 + 0];
    int v1 = g_part[lane * 4 + 1];
    int v2 = g_part[lane * 4 + 2];
    int v3 = g_part[lane * 4 + 3];
    int lsum = v0 + v1 + v2 + v3;
    int inc = lsum;
#pragma unroll
    for (int o = 1; o < 32; o <<= 1) {
        int t = __shfl_up_sync(0xffffffffu, inc, o);
        if (lane >= o) inc += t;
    }
    int excl = inc - lsum;
    g_partsc[lane * 4 + 0] = excl;
    g_partsc[lane * 4 + 1] = excl + v0;
    g_partsc[lane * 4 + 2] = excl + v0 + v1;
    g_partsc[lane * 4 + 3] = excl + v0 + v1 + v2;
}

__global__ void k_rowptr() {
    int i = blockIdx.x * blockDim.x + threadIdx.x;
    if (i < N_NODES) g_rowptr[i] = g_base[i] + g_partsc[i >> 10];
    if (i == 0) g_rowptr[N_NODES] = E2;
}

// ---------------- scatter edges into CSR order --------------------------------
__global__ void k_scatter(const void* ei) {
    int i = blockIdx.x * blockDim.x + threadIdx.x;
    if (i >= E2) return;
    int s, d;
    if (i < E_EDGES) {
        if (g_is64) {
            const long long* p = (const long long*)ei;
            s = (int)p[i]; d = (int)p[E_EDGES + i];
        } else {
            const int* p = (const int*)ei;
            s = p[i]; d = p[E_EDGES + i];
        }
    } else {
        s = d = i - E_EDGES;
    }
    int pos = g_rowptr[d] + atomicAdd(&g_cur[d], 1);
    g_csr_src[pos] = s;
}

// ---------------- layer1: h = x @ W1 (fp16 out), per-node alphas --------------
__global__ __launch_bounds__(256) void k_l1(const float* __restrict__ x,
                                            const float* __restrict__ W1,
                                            const float* __restrict__ as1,
                                            const float* __restrict__ ad1) {
    __shared__ float sW[IN_DIM * HID];   // 32 KB
    __shared__ float sx[32 * IN_DIM];    // 16 KB (reused as sh[32*65])
    int tid = threadIdx.x;
    int node0 = blockIdx.x * 32;
    {
        float4* dw = (float4*)sW; const float4* swg = (const float4*)W1;
        for (int i = tid; i < (IN_DIM * HID) / 4; i += 256) dw[i] = swg[i];
        float4* dx = (float4*)sx;
        const float4* sxg = (const float4*)(x + (size_t)node0 * IN_DIM);
        for (int i = tid; i < (32 * IN_DIM) / 4; i += 256) dx[i] = sxg[i];
    }
    __syncthreads();

    int d = tid & 63, g = tid >> 6;
    float acc[8];
#pragma unroll
    for (int j = 0; j < 8; j++) acc[j] = 0.f;
    for (int k = 0; k < IN_DIM; k += 4) {
        float w0 = sW[(k + 0) * HID + d];
        float w1 = sW[(k + 1) * HID + d];
        float w2 = sW[(k + 2) * HID + d];
        float w3 = sW[(k + 3) * HID + d];
#pragma unroll
        for (int j = 0; j < 8; j++) {
            float4 xv = *(const float4*)&sx[(g * 8 + j) * IN_DIM + k];
            acc[j] = fmaf(w0, xv.x, acc[j]);
            acc[j] = fmaf(w1, xv.y, acc[j]);
            acc[j] = fmaf(w2, xv.z, acc[j]);
            acc[j] = fmaf(w3, xv.w, acc[j]);
        }
    }
    __syncthreads();
    float* sh = sx;
#pragma unroll
    for (int j = 0; j < 8; j++) {
        int n = g * 8 + j;
        sh[n * 65 + d] = acc[j];
        g_h16[(size_t)(node0 + n) * HID + d] = __float2half_rn(acc[j]);
    }
    __syncthreads();
    if (tid < 32) {
        int gn = node0 + tid;
        float s = 0.f, dd = 0.f;
#pragma unroll
        for (int k = 0; k < HID; k++) {
            float hv = sh[tid * 65 + k];
            s  = fmaf(hv, as1[k], s);
            dd = fmaf(hv, ad1[k], dd);
        }
        g_as[gn] = s; g_ad[gn] = dd;
    }
}

// ---------------- CSR aggregate, warp per node --------------------------------
// 4 groups of 8 lanes, one edge each per iteration (4 rows in flight).
// Next csr_src prefetched one iteration ahead -> no load->load chain in-loop.
// Each lane gathers 8 halves (16B) of the 128B fp16 row.
// FUSE_OUT=0: writes elu(agg + b1) to g_agg.  FUSE_OUT=1: full output head.
template <int FUSE_OUT>
__global__ __launch_bounds__(256) void k_agg(const float* __restrict__ bvec,
                                             const float* __restrict__ Wout,
                                             const float* __restrict__ bout,
                                             float* __restrict__ out) {
    int n = blockIdx.x * 8 + (threadIdx.x >> 5);
    if (n >= N_NODES) return;
    int lane = threadIdx.x & 31;
    int grp = lane >> 3, r = lane & 7;       // 4 groups x 8 lanes
    int beg = g_rowptr[n], end = g_rowptr[n + 1];
    float add = g_ad[n];
    float a[8];
#pragma unroll
    for (int i = 0; i < 8; i++) a[i] = 0.f;
    float dsum = 0.f;

    int j = beg + grp;
    int s_nxt = (j < end) ? __ldg(&g_csr_src[j]) : 0;
    for (; j < end; j += 4) {
        int s = s_nxt;
        int jn = j + 4;
        if (jn < end) s_nxt = __ldg(&g_csr_src[jn]);
        float e = __ldg(&g_as[s]) + add;
        e = fmaxf(e, NEG_SLOPE * e);
        float w = __expf(e);
        dsum += w;
        // 16B = 8 halves at r*8
        uint4 u = *(const uint4*)&g_h16[(size_t)s * HID + r * 8];
        float2 f0 = __half22float2(*(__half2*)&u.x);
        float2 f1 = __half22float2(*(__half2*)&u.y);
        float2 f2 = __half22float2(*(__half2*)&u.z);
        float2 f3 = __half22float2(*(__half2*)&u.w);
        a[0] = fmaf(w, f0.x, a[0]); a[1] = fmaf(w, f0.y, a[1]);
        a[2] = fmaf(w, f1.x, a[2]); a[3] = fmaf(w, f1.y, a[3]);
        a[4] = fmaf(w, f2.x, a[4]); a[5] = fmaf(w, f2.y, a[5]);
        a[6] = fmaf(w, f3.x, a[6]); a[7] = fmaf(w, f3.y, a[7]);
    }
    // reduce across the 4 groups (lanes r, r+8, r+16, r+24)
#pragma unroll
    for (int i = 0; i < 8; i++) {
        a[i] += __shfl_xor_sync(0xffffffffu, a[i], 8);
        a[i] += __shfl_xor_sync(0xffffffffu, a[i], 16);
    }
    dsum += __shfl_xor_sync(0xffffffffu, dsum, 8);
    dsum += __shfl_xor_sync(0xffffffffu, dsum, 16);
    float inv = 1.f / dsum;                 // self loop => dsum > 0

    float v[8];
#pragma unroll
    for (int i = 0; i < 8; i++)
        v[i] = elu_f(a[i] * inv + bvec[r * 8 + i]);

    if (FUSE_OUT) {
        float p = 0.f;
#pragma unroll
        for (int i = 0; i < 8; i++) p = fmaf(v[i], Wout[r * 8 + i], p);
        p += __shfl_xor_sync(0xffffffffu, p, 4);
        p += __shfl_xor_sync(0xffffffffu, p, 2);
        p += __shfl_xor_sync(0xffffffffu, p, 1);
        if (lane == 0) out[n] = p + bout[0];
    } else if (grp == 0) {
        float4 o0 = { v[0], v[1], v[2], v[3] };
        float4 o1 = { v[4], v[5], v[6], v[7] };
        *(float4*)&g_agg[(size_t)n * HID + r * 8]     = o0;
        *(float4*)&g_agg[(size_t)n * HID + r * 8 + 4] = o1;
    }
}

// ---------------- layer2: g_agg (pre-activated) @ W2 (fp16 out), new alphas ---
__global__ __launch_bounds__(256) void k_l2(const float* __restrict__ W2,
                                            const float* __restrict__ as2,
                                            const float* __restrict__ ad2) {
    __shared__ float sW[HID * HID];   // 16 KB
    __shared__ float sh1[32 * 68];
    __shared__ float sh2[32 * 65];
    int tid = threadIdx.x;
    int node0 = blockIdx.x * 32;
    {
        float4* dw = (float4*)sW; const float4* swg = (const float4*)W2;
        for (int i = tid; i < (HID * HID) / 4; i += 256) dw[i] = swg[i];
    }
    int d = tid & 63, g = tid >> 6;
#pragma unroll
    for (int j = 0; j < 8; j++) {
        int n = g * 8 + j;
        sh1[n * 68 + d] = g_agg[(size_t)(node0 + n) * HID + d];
    }
    __syncthreads();
    float acc[8];
#pragma unroll
    for (int j = 0; j < 8; j++) acc[j] = 0.f;
    for (int k = 0; k < HID; k += 4) {
        float w0 = sW[(k + 0) * HID + d];
        float w1 = sW[(k + 1) * HID + d];
        float w2 = sW[(k + 2) * HID + d];
        float w3 = sW[(k + 3) * HID + d];
#pragma unroll
        for (int j = 0; j < 8; j++) {
            float4 xv = *(const float4*)&sh1[(g * 8 + j) * 68 + k];
            acc[j] = fmaf(w0, xv.x, acc[j]);
            acc[j] = fmaf(w1, xv.y, acc[j]);
            acc[j] = fmaf(w2, xv.z, acc[j]);
            acc[j] = fmaf(w3, xv.w, acc[j]);
        }
    }
#pragma unroll
    for (int j = 0; j < 8; j++) {
        int n = g * 8 + j;
        sh2[n * 65 + d] = acc[j];
        g_h16[(size_t)(node0 + n) * HID + d] = __float2half_rn(acc[j]);
    }
    __syncthreads();
    if (tid < 32) {
        int gn = node0 + tid;
        float s = 0.f, dd = 0.f;
#pragma unroll
        for (int k = 0; k < HID; k++) {
            float hv = sh2[tid * 65 + k];
            s  = fmaf(hv, as2[k], s);
            dd = fmaf(hv, ad2[k], dd);
        }
        g_as[gn] = s; g_ad[gn] = dd;
    }
}

// ---------------- launch ------------------------------------------------------
extern "C" void kernel_launch(void* const* d_in, const int* in_sizes, int n_in,
                              void* d_out, int out_size) {
    const float* x    = (const float*)d_in[0];
    const void*  ei   = d_in[1];
    const float* W1   = (const float*)d_in[2];
    const float* as1  = (const float*)d_in[3];
    const float* ad1  = (const float*)d_in[4];
    const float* b1   = (const float*)d_in[5];
    const float* W2   = (const float*)d_in[6];
    const float* as2  = (const float*)d_in[7];
    const float* ad2  = (const float*)d_in[8];
    const float* b2   = (const float*)d_in[9];
    const float* Wout = (const float*)d_in[10];
    const float* bout = (const float*)d_in[11];
    float* out = (float*)d_out;

    const int EB = (E2 + 255) / 256;
    const int NB8 = (N_NODES + 7) / 8;

    // CSR build (shared by both layers)
    k_probe<<<1, 256>>>((const int*)ei);
    k_zero<<<(N_NODES + 255) / 256, 256>>>();
    k_hist<<<EB, 256>>>(ei);
    k_scan1<<<NCHUNKS, SCAN_CHUNK>>>();
    k_scan2<<<1, 32>>>();
    k_rowptr<<<(N_NODES + 255) / 256, 256>>>();
    k_scatter<<<EB, 256>>>(ei);

    // layer 1
    k_l1<<<N_NODES / 32, 256>>>(x, W1, as1, ad1);
    k_agg<0><<<NB8, 256>>>(b1, nullptr, nullptr, nullptr);

    // layer 2 + fused output head
    k_l2<<<N_NODES / 32, 256>>>(W2, as2, ad2);
    k_agg<1><<<NB8, 256>>>(b2, Wout, bout, out);
}

// round 15
// speedup vs baseline: 1.0917x; 1.0917x over previous
#include <cuda_runtime.h>
#include <cstdint>

#define N_NODES 100000
#define E_EDGES 1600000
#define E2 (E_EDGES + N_NODES)   // 1,700,000 with self loops
#define HID 64
#define IN_DIM 128
#define NEG_SLOPE 0.2f
#define SCAN_CHUNK 1024
#define NCHUNKS ((N_NODES + SCAN_CHUNK - 1) / SCAN_CHUNK)   // 98

// ---------------- scratch (device globals) ------------------------------------
__device__ float g_h[(size_t)N_NODES * HID];      // fp32 features (gathered)
__device__ float g_agg[(size_t)N_NODES * HID];    // layer1 output: elu(agg+b1)
__device__ float g_as[N_NODES], g_ad[N_NODES];    // per-node alpha_src / alpha_dst
__device__ int   g_csr_src[E2];                   // dst-sorted src indices
__device__ int   g_cnt[N_NODES];                  // per-dst degree histogram
__device__ int   g_cur[N_NODES];                  // scatter cursors
__device__ int   g_base[N_NODES];                 // per-chunk exclusive scan
__device__ int   g_part[128], g_partsc[128];      // chunk partials / scanned
__device__ int   g_rowptr[N_NODES + 1];           // CSR row pointers
__device__ int   g_is64;                          // edge_index dtype flag

// ---------------- helpers -----------------------------------------------------
__device__ __forceinline__ float elu_f(float v) { return v > 0.f ? v : expm1f(v); }

__device__ __forceinline__ int warp_incl_scan(int v) {
    int lane = threadIdx.x & 31;
#pragma unroll
    for (int o = 1; o < 32; o <<= 1) {
        int t = __shfl_up_sync(0xffffffffu, v, o);
        if (lane >= o) v += t;
    }
    return v;
}

// ---------------- dtype probe -------------------------------------------------
__global__ void k_probe(const int* ei32) {
    __shared__ int nz;
    if (threadIdx.x == 0) nz = 0;
    __syncthreads();
    int any = 0;
    for (int i = threadIdx.x; i < 2048; i += 256)
        any |= (ei32[2 * i + 1] != 0);
    if (any) atomicOr(&nz, 1);
    __syncthreads();
    if (threadIdx.x == 0) g_is64 = (nz == 0) ? 1 : 0;
}

// ---------------- histogram by dst (reads edge_index directly) ----------------
__global__ void k_hist(const void* ei) {
    int i = blockIdx.x * blockDim.x + threadIdx.x;
    if (i >= E2) return;
    int d;
    if (i < E_EDGES) {
        d = g_is64 ? (int)((const long long*)ei)[E_EDGES + i]
                   : ((const int*)ei)[E_EDGES + i];
    } else {
        d = i - E_EDGES;
    }
    atomicAdd(&g_cnt[d], 1);
}

// ---------------- two-level scan of histogram ---------------------------------
__global__ __launch_bounds__(SCAN_CHUNK) void k_scan1() {
    __shared__ int wsum[32];
    int b = blockIdx.x;
    int i = b * SCAN_CHUNK + threadIdx.x;
    int lane = threadIdx.x & 31, wid = threadIdx.x >> 5;
    int v = (i < N_NODES) ? g_cnt[i] : 0;
    int inc = warp_incl_scan(v);
    if (lane == 31) wsum[wid] = inc;
    __syncthreads();
    if (wid == 0) wsum[lane] = warp_incl_scan(wsum[lane]);
    __syncthreads();
    int off = wid ? wsum[wid - 1] : 0;
    if (i < N_NODES) g_base[i] = off + inc - v;
    if (threadIdx.x == SCAN_CHUNK - 1) g_part[b] = wsum[31];
}

__global__ __launch_bounds__(32) void k_scan2() {
    int lane = threadIdx.x;
    int v0 = g_part[lane * 4 + 0];
    int v1 = g_part[lane * 4 + 1];
    int v2 = g_part[lane * 4 + 2];
    int v3 = g_part[lane * 4 + 3];
    int lsum = v0 + v1 + v2 + v3;
    int inc = lsum;
#pragma unroll
    for (int o = 1; o < 32; o <<= 1) {
        int t = __shfl_up_sync(0xffffffffu, inc, o);
        if (lane >= o) inc += t;
    }
    int excl = inc - lsum;
    g_partsc[lane * 4 + 0] = excl;
    g_partsc[lane * 4 + 1] = excl + v0;
    g_partsc[lane * 4 + 2] = excl + v0 + v1;
    g_partsc[lane * 4 + 3] = excl + v0 + v1 + v2;
}

__global__ void k_rowptr() {
    int i = blockIdx.x * blockDim.x + threadIdx.x;
    if (i < N_NODES) g_rowptr[i] = g_base[i] + g_partsc[i >> 10];
    if (i == 0) g_rowptr[N_NODES] = E2;
}

// ---------------- scatter edges into CSR order --------------------------------
__global__ void k_scatter(const void* ei) {
    int i = blockIdx.x * blockDim.x + threadIdx.x;
    if (i >= E2) return;
    int s, d;
    if (i < E_EDGES) {
        if (g_is64) {
            const long long* p = (const long long*)ei;
            s = (int)p[i]; d = (int)p[E_EDGES + i];
        } else {
            const int* p = (const int*)ei;
            s = p[i]; d = p[E_EDGES + i];
        }
    } else {
        s = d = i - E_EDGES;
    }
    int pos = g_rowptr[d] + atomicAdd(&g_cur[d], 1);
    g_csr_src[pos] = s;
}

// ---------------- layer1: h = x @ W1, per-node alphas -------------------------
__global__ __launch_bounds__(256) void k_l1(const float* __restrict__ x,
                                            const float* __restrict__ W1,
                                            const float* __restrict__ as1,
                                            const float* __restrict__ ad1) {
    __shared__ float sW[IN_DIM * HID];   // 32 KB
    __shared__ float sx[32 * IN_DIM];    // 16 KB (reused as sh[32*65])
    int tid = threadIdx.x;
    int node0 = blockIdx.x * 32;
    {
        float4* dw = (float4*)sW; const float4* swg = (const float4*)W1;
        for (int i = tid; i < (IN_DIM * HID) / 4; i += 256) dw[i] = swg[i];
        float4* dx = (float4*)sx;
        const float4* sxg = (const float4*)(x + (size_t)node0 * IN_DIM);
        for (int i = tid; i < (32 * IN_DIM) / 4; i += 256) dx[i] = sxg[i];
    }
    __syncthreads();

    int d = tid & 63, g = tid >> 6;
    float acc[8];
#pragma unroll
    for (int j = 0; j < 8; j++) acc[j] = 0.f;
    for (int k = 0; k < IN_DIM; k += 4) {
        float w0 = sW[(k + 0) * HID + d];
        float w1 = sW[(k + 1) * HID + d];
        float w2 = sW[(k + 2) * HID + d];
        float w3 = sW[(k + 3) * HID + d];
#pragma unroll
        for (int j = 0; j < 8; j++) {
            float4 xv = *(const float4*)&sx[(g * 8 + j) * IN_DIM + k];
            acc[j] = fmaf(w0, xv.x, acc[j]);
            acc[j] = fmaf(w1, xv.y, acc[j]);
            acc[j] = fmaf(w2, xv.z, acc[j]);
            acc[j] = fmaf(w3, xv.w, acc[j]);
        }
    }
    __syncthreads();
    float* sh = sx;
#pragma unroll
    for (int j = 0; j < 8; j++) {
        int n = g * 8 + j;
        sh[n * 65 + d] = acc[j];
        g_h[(size_t)(node0 + n) * HID + d] = acc[j];
    }
    __syncthreads();
    if (tid < 32) {
        int gn = node0 + tid;
        float s = 0.f, dd = 0.f;
#pragma unroll
        for (int k = 0; k < HID; k++) {
            float hv = sh[tid * 65 + k];
            s  = fmaf(hv, as1[k], s);
            dd = fmaf(hv, ad1[k], dd);
        }
        g_as[gn] = s; g_ad[gn] = dd;
    }
}

// ---------------- CSR aggregate (round-4 proven loop) + fused epilogues -------
// warp per dst node; two 16-lane groups, one edge each per iteration.
// FUSE_OUT=0: writes elu(agg + b1) to g_agg.  FUSE_OUT=1: full output head.
template <int FUSE_OUT>
__global__ __launch_bounds__(256) void k_agg(const float* __restrict__ bvec,
                                             const float* __restrict__ Wout,
                                             const float* __restrict__ bout,
                                             float* __restrict__ out) {
    int n = blockIdx.x * 8 + (threadIdx.x >> 5);
    if (n >= N_NODES) return;
    int lane = threadIdx.x & 31;
    int grp = lane >> 4, r = lane & 15;
    int beg = g_rowptr[n], end = g_rowptr[n + 1];
    float add = g_ad[n];
    float ax = 0.f, ay = 0.f, az = 0.f, aw = 0.f, dsum = 0.f;
    for (int j = beg + grp; j < end; j += 2) {
        int s = g_csr_src[j];
        float e = g_as[s] + add;
        e = fmaxf(e, NEG_SLOPE * e);
        float ex = __expf(e);
        const float4 hv = *(const float4*)&g_h[(size_t)s * HID + r * 4];
        ax = fmaf(ex, hv.x, ax);
        ay = fmaf(ex, hv.y, ay);
        az = fmaf(ex, hv.z, az);
        aw = fmaf(ex, hv.w, aw);
        dsum += ex;
    }
    ax += __shfl_xor_sync(0xffffffffu, ax, 16);
    ay += __shfl_xor_sync(0xffffffffu, ay, 16);
    az += __shfl_xor_sync(0xffffffffu, az, 16);
    aw += __shfl_xor_sync(0xffffffffu, aw, 16);
    dsum += __shfl_xor_sync(0xffffffffu, dsum, 16);
    float inv = 1.f / dsum;                 // self loop => dsum > 0

    float v0 = elu_f(ax * inv + bvec[r * 4 + 0]);
    float v1 = elu_f(ay * inv + bvec[r * 4 + 1]);
    float v2 = elu_f(az * inv + bvec[r * 4 + 2]);
    float v3 = elu_f(aw * inv + bvec[r * 4 + 3]);

    if (FUSE_OUT) {
        float p = v0 * Wout[r * 4 + 0] + v1 * Wout[r * 4 + 1]
                + v2 * Wout[r * 4 + 2] + v3 * Wout[r * 4 + 3];
#pragma unroll
        for (int o = 8; o > 0; o >>= 1) p += __shfl_xor_sync(0xffffffffu, p, o);
        if (lane == 0) out[n] = p + bout[0];
    } else if (grp == 0) {
        float4 o4 = { v0, v1, v2, v3 };
        *(float4*)&g_agg[(size_t)n * HID + r * 4] = o4;
    }
}

// ---------------- layer2: g_agg (pre-activated) @ W2, new alphas --------------
__global__ __launch_bounds__(256) void k_l2(const float* __restrict__ W2,
                                            const float* __restrict__ as2,
                                            const float* __restrict__ ad2) {
    __shared__ float sW[HID * HID];   // 16 KB
    __shared__ float sh1[32 * 68];
    __shared__ float sh2[32 * 65];
    int tid = threadIdx.x;
    int node0 = blockIdx.x * 32;
    {
        float4* dw = (float4*)sW; const float4* swg = (const float4*)W2;
        for (int i = tid; i < (HID * HID) / 4; i += 256) dw[i] = swg[i];
    }
    int d = tid & 63, g = tid >> 6;
#pragma unroll
    for (int j = 0; j < 8; j++) {
        int n = g * 8 + j;
        sh1[n * 68 + d] = g_agg[(size_t)(node0 + n) * HID + d];
    }
    __syncthreads();
    float acc[8];
#pragma unroll
    for (int j = 0; j < 8; j++) acc[j] = 0.f;
    for (int k = 0; k < HID; k += 4) {
        float w0 = sW[(k + 0) * HID + d];
        float w1 = sW[(k + 1) * HID + d];
        float w2 = sW[(k + 2) * HID + d];
        float w3 = sW[(k + 3) * HID + d];
#pragma unroll
        for (int j = 0; j < 8; j++) {
            float4 xv = *(const float4*)&sh1[(g * 8 + j) * 68 + k];
            acc[j] = fmaf(w0, xv.x, acc[j]);
            acc[j] = fmaf(w1, xv.y, acc[j]);
            acc[j] = fmaf(w2, xv.z, acc[j]);
            acc[j] = fmaf(w3, xv.w, acc[j]);
        }
    }
#pragma unroll
    for (int j = 0; j < 8; j++) {
        int n = g * 8 + j;
        sh2[n * 65 + d] = acc[j];
        g_h[(size_t)(node0 + n) * HID + d] = acc[j];
    }
    __syncthreads();
    if (tid < 32) {
        int gn = node0 + tid;
        float s = 0.f, dd = 0.f;
#pragma unroll
        for (int k = 0; k < HID; k++) {
            float hv = sh2[tid * 65 + k];
            s  = fmaf(hv, as2[k], s);
            dd = fmaf(hv, ad2[k], dd);
        }
        g_as[gn] = s; g_ad[gn] = dd;
    }
}

// ---------------- launch: forked capture (CSR build || layer1 GEMM) -----------
extern "C" void kernel_launch(void* const* d_in, const int* in_sizes, int n_in,
                              void* d_out, int out_size) {
    const float* x    = (const float*)d_in[0];
    const void*  ei   = d_in[1];
    const float* W1   = (const float*)d_in[2];
    const float* as1  = (const float*)d_in[3];
    const float* ad1  = (const float*)d_in[4];
    const float* b1   = (const float*)d_in[5];
    const float* W2   = (const float*)d_in[6];
    const float* as2  = (const float*)d_in[7];
    const float* ad2  = (const float*)d_in[8];
    const float* b2   = (const float*)d_in[9];
    const float* Wout = (const float*)d_in[10];
    const float* bout = (const float*)d_in[11];
    float* out = (float*)d_out;

    const int EB = (E2 + 255) / 256;
    const int NB8 = (N_NODES + 7) / 8;

    static cudaStream_t sB = nullptr;
    static cudaEvent_t evF = nullptr, evJ = nullptr;
    static void *p_cnt = nullptr, *p_cur = nullptr;
    if (sB == nullptr) {
        cudaStreamCreateWithFlags(&sB, cudaStreamNonBlocking);
        cudaEventCreateWithFlags(&evF, cudaEventDisableTiming);
        cudaEventCreateWithFlags(&evJ, cudaEventDisableTiming);
        cudaGetSymbolAddress(&p_cnt, g_cnt);
        cudaGetSymbolAddress(&p_cur, g_cur);
    }

    cudaStream_t s0 = (cudaStream_t)0;

    // fork: CSR build on sB
    cudaEventRecord(evF, s0);
    cudaStreamWaitEvent(sB, evF, 0);
    cudaMemsetAsync(p_cnt, 0, N_NODES * sizeof(int), sB);
    cudaMemsetAsync(p_cur, 0, N_NODES * sizeof(int), sB);
    k_probe<<<1, 256, 0, sB>>>((const int*)ei);
    k_hist<<<EB, 256, 0, sB>>>(ei);
    k_scan1<<<NCHUNKS, SCAN_CHUNK, 0, sB>>>();
    k_scan2<<<1, 32, 0, sB>>>();
    k_rowptr<<<(N_NODES + 255) / 256, 256, 0, sB>>>();
    k_scatter<<<EB, 256, 0, sB>>>(ei);
    cudaEventRecord(evJ, sB);

    // concurrently: layer-1 GEMM + alphas on the main stream
    k_l1<<<N_NODES / 32, 256, 0, s0>>>(x, W1, as1, ad1);

    // join, then the serial tail
    cudaStreamWaitEvent(s0, evJ, 0);
    k_agg<0><<<NB8, 256, 0, s0>>>(b1, nullptr, nullptr, nullptr);
    k_l2<<<N_NODES / 32, 256, 0, s0>>>(W2, as2, ad2);
    k_agg<1><<<NB8, 256, 0, s0>>>(b2, Wout, bout, out);
}